// round 15
// baseline (speedup 1.0000x reference)
#include <cuda_runtime.h>
#include <cuda_fp16.h>
#include <math.h>
#include <stdint.h>

// ---------------------------------------------------------------------------
// BolmoLocalLayer: xLSTM mixer + SwiGLU MLP.  B=2, S=2048, D=2048, H=8.
// Round 15: R14 + N-split down-projection so the split-K reducer of half A
// overlaps the GEMM of half B (bit-identical math to R14).
// ---------------------------------------------------------------------------

#define Bv   2
#define Sv   2048
#define Dv   2048
#define Hv   8
#define QKv  1024
#define DQK  128
#define DVv  256
#define FFv  8192
#define Mv   (Bv*Sv)      // 4096
#define BHv  (Bv*Hv)      // 16
#define QKVO 6144         // merged projection width: q(1024)|k(1024)|v(2048)|og(2048)
#define KSPL 4            // down-proj split-K factor

// ----------------------------- fp32 scratch --------------------------------
#define F_HIN   ((size_t)0)
#define F_X1    (F_HIN  + (size_t)Mv*Dv)
#define F_IPRE  (F_X1   + (size_t)Mv*Dv)
#define F_FPRE  (F_IPRE + (size_t)BHv*Sv)
#define F_A     (F_FPRE + (size_t)BHv*Sv)
#define F_G     (F_A    + (size_t)BHv*Sv)
#define F_NFL   (F_G    + (size_t)BHv*Sv)
#define F_TOTAL (F_NFL  + (size_t)BHv*Sv)
__device__ __align__(256) float g_f32[F_TOTAL];

// ----------------------------- fp16 scratch --------------------------------
#define P_HIN   ((size_t)0)
#define P_HOUT  (P_HIN   + (size_t)Mv*Dv)
#define P_H2    (P_HOUT  + (size_t)Mv*Dv)
#define P_ACT   (P_H2    + (size_t)Mv*Dv)
#define P_GATE  (P_ACT   + (size_t)Mv*FFv)
#define P_PART  (P_GATE  + (size_t)Mv*FFv)
#define P_WQ    (P_PART  + (size_t)KSPL*Mv*Dv)
#define P_WK    (P_WQ    + (size_t)QKv*Dv)
#define P_WV    (P_WK    + (size_t)QKv*Dv)
#define P_WOG   (P_WV    + (size_t)Dv*Dv)
#define P_WOUT  (P_WOG   + (size_t)Dv*Dv)
#define P_WG    (P_WOUT  + (size_t)Dv*Dv)
#define P_WU    (P_WG    + (size_t)FFv*Dv)
#define P_WD    (P_WU    + (size_t)FFv*Dv)
#define P_QKVO  (P_WD    + (size_t)Dv*FFv)
#define P_TOTAL (P_QKVO  + (size_t)Mv*QKVO)
__device__ __align__(256) __half g_fp16[P_TOTAL];

// ----------------------------- helpers -------------------------------------
__device__ __forceinline__ uint32_t smem_u32(const void* p) {
    uint32_t a;
    asm("{ .reg .u64 t; cvta.to.shared.u64 t, %1; cvt.u32.u64 %0, t; }"
        : "=r"(a) : "l"(p));
    return a;
}

__device__ __forceinline__ void cp16(uint32_t sa, const void* g) {
    asm volatile("cp.async.ca.shared.global [%0], [%1], 16;"
                 :: "r"(sa), "l"(g) : "memory");
}
#define CP_COMMIT() asm volatile("cp.async.commit_group;" ::: "memory")
#define CP_WAIT1()  asm volatile("cp.async.wait_group 1;" ::: "memory")
#define CP_WAIT0()  asm volatile("cp.async.wait_group 0;" ::: "memory")

__device__ __forceinline__ void ldsm4(uint32_t* r, uint32_t addr) {
    asm volatile("ldmatrix.sync.aligned.m8n8.x4.shared.b16 {%0,%1,%2,%3}, [%4];"
                 : "=r"(r[0]), "=r"(r[1]), "=r"(r[2]), "=r"(r[3]) : "r"(addr));
}
__device__ __forceinline__ void ldsm4t(uint32_t* r, uint32_t addr) {
    asm volatile("ldmatrix.sync.aligned.m8n8.x4.trans.shared.b16 {%0,%1,%2,%3}, [%4];"
                 : "=r"(r[0]), "=r"(r[1]), "=r"(r[2]), "=r"(r[3]) : "r"(addr));
}

__device__ __forceinline__ void mma16816(float* c, const uint32_t* a,
                                         uint32_t b0, uint32_t b1) {
    asm volatile(
        "mma.sync.aligned.m16n8k16.row.col.f32.f16.f16.f32 "
        "{%0,%1,%2,%3}, {%4,%5,%6,%7}, {%8,%9}, {%0,%1,%2,%3};"
        : "+f"(c[0]), "+f"(c[1]), "+f"(c[2]), "+f"(c[3])
        : "r"(a[0]), "r"(a[1]), "r"(a[2]), "r"(a[3]), "r"(b0), "r"(b1));
}

// --------------------------- HMMA GEMM (1-pass fp16) ------------------------
// CTA tile 256x128, warp tile 64x64.  3-stage cp.async pipeline.
// EPI 0: C fp32 = acc.        EPI 1: C fp32 = aux + acc.
// EPI 3: CH fp16 = acc.       EPI 4: CH fp16 = silu(auxh) * acc.
// EPI 6: split-K partial fp16 — plane z (blockIdx.z), K-slice of K/KSPL.
#define KCH    64
#define RSTRB  144
#define ATILEB (256*RSTRB)
#define BTILEB (128*RSTRB)
#define NSTG   3
#define STAGEB (ATILEB + BTILEB)        // 55296
#define GSMEM  (NSTG*STAGEB)            // 165888

template<int EPI>
__global__ void __launch_bounds__(256) tgemm_kernel(
    const __half* __restrict__ AH, const __half* __restrict__ BH,
    const float* __restrict__ aux, const __half* __restrict__ auxh,
    float* __restrict__ C, __half* __restrict__ CH, int N, int K)
{
    extern __shared__ char smem[];
    const uint32_t sb = smem_u32(smem);
    const int tid = threadIdx.x;
    const int lane = tid & 31;
    const int wid = tid >> 5;
    const int wm = wid & 3;
    const int wn = wid >> 2;
    const int m0 = blockIdx.y * 256;
    const int n0 = blockIdx.x * 128;

    const int kslice = (EPI == 6) ? (K / KSPL) : K;
    const int koff   = (EPI == 6) ? ((int)blockIdx.z * kslice) : 0;

    const __half* srcA = AH + (size_t)m0 * K + koff;
    const __half* srcB = BH + (size_t)n0 * K + koff;

    float acc[4][8][4];
    #pragma unroll
    for (int i = 0; i < 4; i++)
        #pragma unroll
        for (int j = 0; j < 8; j++)
            #pragma unroll
            for (int e = 0; e < 4; e++) acc[i][j][e] = 0.f;

    const int NC = kslice / KCH;

    auto load_chunk = [&](int c, int s) {
        const __half* ga = srcA + c * KCH;
        uint32_t abase = sb + (uint32_t)(s * STAGEB);
        #pragma unroll
        for (int i = 0; i < 8; i++) {
            int seg = tid + 256 * i;
            int row = seg >> 3, s8 = seg & 7;
            cp16(abase + (uint32_t)(row * RSTRB + s8 * 16),
                 ga + (size_t)row * K + s8 * 8);
        }
        const __half* gb = srcB + c * KCH;
        uint32_t bbase = abase + ATILEB;
        #pragma unroll
        for (int i = 0; i < 4; i++) {
            int seg = tid + 256 * i;
            int row = seg >> 3, s8 = seg & 7;
            cp16(bbase + (uint32_t)(row * RSTRB + s8 * 16),
                 gb + (size_t)row * K + s8 * 8);
        }
    };

    load_chunk(0, 0); CP_COMMIT();
    load_chunk(1, 1); CP_COMMIT();

    const int a_r = (lane & 15);
    const int a_k = (lane >> 4) * 8;
    const int b_r = (lane & 7) + (lane >> 4) * 8;
    const int b_k = ((lane >> 3) & 1) * 8;

    for (int c = 0; c < NC; c++) {
        const int s = c % NSTG;
        if (c + 1 < NC) CP_WAIT1(); else CP_WAIT0();
        __syncthreads();
        if (c + 2 < NC) { load_chunk(c + 2, (c + 2) % NSTG); CP_COMMIT(); }

        const uint32_t bA = sb + s * STAGEB;
        const uint32_t bB = bA + ATILEB;

        #pragma unroll
        for (int kk = 0; kk < KCH; kk += 16) {
            uint32_t aH[4][4], bf[4][4];
            #pragma unroll
            for (int mt = 0; mt < 4; mt++) {
                int row = wm * 64 + mt * 16 + a_r;
                ldsm4(aH[mt], bA + (uint32_t)(row * RSTRB + (kk + a_k) * 2));
            }
            #pragma unroll
            for (int j = 0; j < 4; j++) {
                int row = wn * 64 + j * 16 + b_r;
                ldsm4(bf[j], bB + (uint32_t)(row * RSTRB + (kk + b_k) * 2));
            }
            #pragma unroll
            for (int mt = 0; mt < 4; mt++)
                #pragma unroll
                for (int j = 0; j < 4; j++) {
                    mma16816(acc[mt][2*j],   aH[mt], bf[j][0], bf[j][1]);
                    mma16816(acc[mt][2*j+1], aH[mt], bf[j][2], bf[j][3]);
                }
        }
    }

    __half* CHbase = CH;
    if (EPI == 6) CHbase = CH + (size_t)blockIdx.z * Mv * Dv;

    const int mrow = m0 + wm * 64;
    const int ncol = n0 + wn * 64;
    #pragma unroll
    for (int mt = 0; mt < 4; mt++) {
        #pragma unroll
        for (int nt = 0; nt < 8; nt++) {
            int r0 = mrow + mt * 16 + (lane >> 2);
            int r1 = r0 + 8;
            int cc = ncol + nt * 8 + (lane & 3) * 2;
            float* a = acc[mt][nt];
            size_t i0 = (size_t)r0 * N + cc;
            size_t i1 = (size_t)r1 * N + cc;
            if (EPI == 0) {
                *(float2*)(C + i0) = make_float2(a[0], a[1]);
                *(float2*)(C + i1) = make_float2(a[2], a[3]);
            } else if (EPI == 1) {
                float2 x0 = *(const float2*)(aux + i0);
                float2 x1 = *(const float2*)(aux + i1);
                *(float2*)(C + i0) = make_float2(a[0] + x0.x, a[1] + x0.y);
                *(float2*)(C + i1) = make_float2(a[2] + x1.x, a[3] + x1.y);
            } else if (EPI == 4) {
                __half2 gh0 = *(const __half2*)(auxh + i0);
                __half2 gh1 = *(const __half2*)(auxh + i1);
                float g0x = __half2float(__low2half(gh0)), g0y = __half2float(__high2half(gh0));
                float g1x = __half2float(__low2half(gh1)), g1y = __half2float(__high2half(gh1));
                float v00 = a[0] * (g0x / (1.f + __expf(-g0x)));
                float v01 = a[1] * (g0y / (1.f + __expf(-g0y)));
                float v10 = a[2] * (g1x / (1.f + __expf(-g1x)));
                float v11 = a[3] * (g1y / (1.f + __expf(-g1y)));
                *(__half2*)(CH + i0) = __floats2half2_rn(v00, v01);
                *(__half2*)(CH + i1) = __floats2half2_rn(v10, v11);
            } else {   // EPI 3 or 6: plain fp16 store
                *(__half2*)(CHbase + i0) = __floats2half2_rn(a[0], a[1]);
                *(__half2*)(CHbase + i1) = __floats2half2_rn(a[2], a[3]);
            }
        }
    }
}

// -------- split-K reduce over one N-half: out = x1 + sum(fp16 partials) -----
// Covers columns [coff, coff+1024).  grid = Mv*256/256 blocks.
__global__ void addredh_kernel(const float* __restrict__ x1,
                               const __half* __restrict__ P,
                               float* __restrict__ out, int coff)
{
    int idx = blockIdx.x * 256 + threadIdx.x;     // 0 .. Mv*256-1
    int row = idx >> 8;
    int c4  = (idx & 255) * 4;
    size_t i = (size_t)row * Dv + coff + c4;
    float4 r = *(const float4*)(x1 + i);
    #pragma unroll
    for (int z = 0; z < KSPL; z++) {
        const __half2* p2 = (const __half2*)(P + (size_t)z * Mv * Dv + i);
        __half2 a = p2[0], b = p2[1];
        r.x += __half2float(__low2half(a));
        r.y += __half2float(__high2half(a));
        r.z += __half2float(__low2half(b));
        r.w += __half2float(__high2half(b));
    }
    *(float4*)(out + i) = r;
}

// ---------------- weight transpose -> fp16 ---------------------------------
__global__ void wsplit_kernel(const float* __restrict__ W,
                              __half* __restrict__ TH, int K, int N)
{
    __shared__ float t[32][33];
    int tx = threadIdx.x, ty = threadIdx.y;
    int n0 = blockIdx.x * 32, k0 = blockIdx.y * 32;
    #pragma unroll
    for (int j = 0; j < 4; j++)
        t[ty + 8 * j][tx] = W[(size_t)(k0 + ty + 8 * j) * N + n0 + tx];
    __syncthreads();
    #pragma unroll
    for (int j = 0; j < 4; j++) {
        float v = t[tx][ty + 8 * j];
        TH[(size_t)(n0 + ty + 8 * j) * K + k0 + tx] = __float2half_rn(v);
    }
}

// --------------------------- RMSNorm (-> fp16, optional fp32) ---------------
template<int WRITE_F32>
__global__ void rmsnorm_kernel(const float* __restrict__ x, const float* __restrict__ w,
                               float* __restrict__ out, __half* __restrict__ oh)
{
    int row = blockIdx.x;
    int tid = threadIdx.x;
    const float4* xr = (const float4*)(x + (size_t)row * Dv);
    float4 v0 = xr[tid];
    float4 v1 = xr[tid + 256];
    float ss = v0.x*v0.x + v0.y*v0.y + v0.z*v0.z + v0.w*v0.w
             + v1.x*v1.x + v1.y*v1.y + v1.z*v1.z + v1.w*v1.w;
    #pragma unroll
    for (int o = 16; o > 0; o >>= 1) ss += __shfl_xor_sync(0xffffffffu, ss, o);
    __shared__ float red[8];
    int wp = tid >> 5, lane = tid & 31;
    if (lane == 0) red[wp] = ss;
    __syncthreads();
    float tot = 0.f;
    #pragma unroll
    for (int i = 0; i < 8; i++) tot += red[i];
    float inv = rsqrtf(tot * (1.f / Dv) + 1e-6f);
    const float4* wr = (const float4*)w;
    #pragma unroll
    for (int half_ = 0; half_ < 2; half_++) {
        float4 v = half_ ? v1 : v0;
        float4 ww = wr[tid + 256 * half_];
        float r[4] = { v.x*inv*ww.x, v.y*inv*ww.y, v.z*inv*ww.z, v.w*inv*ww.w };
        size_t idx = (size_t)row * Dv + (tid + 256 * half_) * 4;
        if (WRITE_F32) *(float4*)(out + idx) = make_float4(r[0], r[1], r[2], r[3]);
        __half2 h0 = __floats2half2_rn(r[0], r[1]);
        __half2 h1 = __floats2half2_rn(r[2], r[3]);
        *(__half2*)(oh + idx) = h0;
        *(__half2*)(oh + idx + 2) = h1;
    }
}

// --------------------------- i/f gate projections ---------------------------
__device__ __forceinline__ float softcap15(float x) {
    return 15.f * tanhf(x * (1.f / 15.f));
}

__global__ void gates_kernel(const float* __restrict__ hin,
                             const float* __restrict__ w_ig, const float* __restrict__ b_ig,
                             const float* __restrict__ w_fg, const float* __restrict__ b_fg,
                             float* __restrict__ ipre, float* __restrict__ fpre)
{
    int row = blockIdx.x;
    int tid = threadIdx.x;
    float pi[8], pf[8];
    #pragma unroll
    for (int h = 0; h < 8; h++) { pi[h] = 0.f; pf[h] = 0.f; }
    const float* xr = hin + (size_t)row * Dv;
    for (int d = tid; d < Dv; d += 256) {
        float xv = xr[d];
        #pragma unroll
        for (int h = 0; h < 8; h++) {
            pi[h] += xv * w_ig[d * 8 + h];
            pf[h] += xv * w_fg[d * 8 + h];
        }
    }
    #pragma unroll
    for (int h = 0; h < 8; h++) {
        #pragma unroll
        for (int o = 16; o > 0; o >>= 1) {
            pi[h] += __shfl_xor_sync(0xffffffffu, pi[h], o);
            pf[h] += __shfl_xor_sync(0xffffffffu, pf[h], o);
        }
    }
    __shared__ float sred[8][16];
    int wp = tid >> 5, lane = tid & 31;
    if (lane == 0) {
        #pragma unroll
        for (int h = 0; h < 8; h++) { sred[wp][h] = pi[h]; sred[wp][8 + h] = pf[h]; }
    }
    __syncthreads();
    if (tid < 16) {
        float s = 0.f;
        #pragma unroll
        for (int w8 = 0; w8 < 8; w8++) s += sred[w8][tid];
        int h = tid & 7;
        bool isf = (tid >= 8);
        float bias = isf ? b_fg[h] : b_ig[h];
        float val = softcap15(s + bias);
        int b = row >> 11;
        int sp = row & (Sv - 1);
        int bh = b * Hv + h;
        (isf ? fpre : ipre)[bh * Sv + sp] = val;
    }
}

// --------------------------- gate scans ------------------------------------
__global__ void scan_kernel(const float* __restrict__ ipre, const float* __restrict__ fpre,
                            float* __restrict__ aout, float* __restrict__ Gout,
                            float* __restrict__ nflout)
{
    int bh = blockIdx.x;
    int tid = threadIdx.x;
    __shared__ float bufA[2048], bufB[2048], fc[2048];

    for (int i = tid; i < 2048; i += 1024) {
        float f = fpre[bh * Sv + i];
        bufA[i] = fminf(f, 0.f) - log1pf(expf(-fabsf(f)));
    }
    __syncthreads();
    float* src = bufA; float* dst = bufB;
    for (int off = 1; off < 2048; off <<= 1) {
        for (int i = tid; i < 2048; i += 1024)
            dst[i] = src[i] + ((i >= off) ? src[i - off] : 0.f);
        __syncthreads();
        float* t = src; src = dst; dst = t;
    }
    for (int i = tid; i < 2048; i += 1024) fc[i] = src[i];
    __syncthreads();
    for (int i = tid; i < 2048; i += 1024) {
        float a = ipre[bh * Sv + i] - fc[i];
        aout[bh * Sv + i] = a;
        dst[i] = a;
    }
    __syncthreads();
    { float* t = src; src = dst; dst = t; }
    for (int off = 1; off < 2048; off <<= 1) {
        for (int i = tid; i < 2048; i += 1024)
            dst[i] = fmaxf(src[i], (i >= off) ? src[i - off] : -1e30f);
        __syncthreads();
        float* t = src; src = dst; dst = t;
    }
    for (int i = tid; i < 2048; i += 1024) {
        float G = src[i];
        Gout[bh * Sv + i] = G;
        nflout[bh * Sv + i] = expf(-(fc[i] + G));
    }
}

// ------------------ HMMA mLSTM attention + fused head-norm ------------------
#define AQ_STRB 272
#define AV_STRB 528
#define ATT_Q_OFF   0
#define ATT_K_OFF   (64*AQ_STRB)
#define ATT_V_OFF   (ATT_K_OFF + 64*AQ_STRB)
#define ATT_WCOL    (ATT_V_OFF + 64*AV_STRB)
#define ATT_C0      (ATT_WCOL + 2048*4)
#define ATT_GT      (ATT_C0 + 32*4)
#define ATT_NF      (ATT_GT + 64*4)
#define ATT_BYTES   (ATT_NF + 64*4)

__global__ void __launch_bounds__(128, 2) attn_kernel(
    const __half* __restrict__ qkvo,
    const float* __restrict__ av, const float* __restrict__ Gv,
    const float* __restrict__ nfv, const float* __restrict__ mh_w,
    __half* __restrict__ houtp)
{
    extern __shared__ char smem[];
    const uint32_t sb = smem_u32(smem);
    float* wcol = (float*)(smem + ATT_WCOL);
    float* c0s  = (float*)(smem + ATT_C0);
    float* gts  = (float*)(smem + ATT_GT);
    float* nfs  = (float*)(smem + ATT_NF);

    const int bh = blockIdx.y;
    const int bb = bh >> 3, hh = bh & 7;
    const int t0 = ((int)gridDim.x - 1 - (int)blockIdx.x) * 64;
    const int tid = threadIdx.x, lane = tid & 31, wid = tid >> 5;
    const int nst = (t0 >> 6) + 1;
    const int nS = t0 + 64;

    const __half* qbase = qkvo + (size_t)(bb * Sv + t0) * QKVO + hh * DQK;
    #pragma unroll
    for (int i = 0; i < 8; i++) {
        int seg = tid + 128 * i;
        int row = seg >> 4, s16 = seg & 15;
        cp16(sb + ATT_Q_OFF + (uint32_t)(row * AQ_STRB + s16 * 16),
             qbase + (size_t)row * QKVO + s16 * 8);
    }
    CP_COMMIT();

    for (int s = tid; s < nS; s += 128) wcol[s] = av[(size_t)bh * Sv + s];
    if (tid < 64) {
        gts[tid] = Gv[(size_t)bh * Sv + t0 + tid];
        nfs[tid] = nfv[(size_t)bh * Sv + t0 + tid];
    }
    __syncthreads();
    if (tid < nst) {
        float m = -1e30f;
        #pragma unroll 8
        for (int i = 0; i < 64; i++) m = fmaxf(m, wcol[tid * 64 + i]);
        c0s[tid] = m;
    }
    __syncthreads();
    const float invsq = 0.08838834764831845f;
    for (int s = tid; s < nS; s += 128)
        wcol[s] = __expf(wcol[s] - c0s[s >> 6]) * invsq;
    __syncthreads();

    const int qr = lane >> 2;
    const int r0 = wid * 16 + qr, r1 = r0 + 8;
    const float gt0 = gts[r0], gt1 = gts[r1];

    const int a_r = lane & 15, a_k = (lane >> 4) * 8;
    const int b_r = (lane & 7) + (lane >> 4) * 8;
    const int b_k = ((lane >> 3) & 1) * 8;
    const int v_k = (lane & 7) + ((lane >> 3) & 1) * 8;
    const int v_n = (lane >> 4) * 8;

    float acc[32][4];
    #pragma unroll
    for (int f = 0; f < 32; f++)
        #pragma unroll
        for (int e = 0; e < 4; e++) acc[f][e] = 0.f;
    float rsa0 = 0.f, rsa1 = 0.f;

    for (int st = 0; st < nst; st++) {
        const int s0 = st << 6;
        __syncthreads();
        const __half* kbase = qkvo + (size_t)(bb * Sv + s0) * QKVO + QKv + hh * DQK;
        #pragma unroll
        for (int i = 0; i < 8; i++) {
            int seg = tid + 128 * i;
            int row = seg >> 4, s16 = seg & 15;
            cp16(sb + ATT_K_OFF + (uint32_t)(row * AQ_STRB + s16 * 16),
                 kbase + (size_t)row * QKVO + s16 * 8);
        }
        const __half* vbase = qkvo + (size_t)(bb * Sv + s0) * QKVO + 2 * QKv + hh * DVv;
        #pragma unroll
        for (int i = 0; i < 16; i++) {
            int seg = tid + 128 * i;
            int row = seg >> 5, s16 = seg & 31;
            cp16(sb + ATT_V_OFF + (uint32_t)(row * AV_STRB + s16 * 16),
                 vbase + (size_t)row * QKVO + s16 * 8);
        }
        CP_COMMIT(); CP_WAIT0();
        __syncthreads();

        float sc[8][4];
        #pragma unroll
        for (int j = 0; j < 8; j++)
            #pragma unroll
            for (int e = 0; e < 4; e++) sc[j][e] = 0.f;
        #pragma unroll
        for (int ks16 = 0; ks16 < 8; ks16++) {
            uint32_t aq[4];
            ldsm4(aq, sb + ATT_Q_OFF +
                  (uint32_t)((wid * 16 + a_r) * AQ_STRB + (ks16 * 16 + a_k) * 2));
            #pragma unroll
            for (int j2 = 0; j2 < 4; j2++) {
                uint32_t bk[4];
                ldsm4(bk, sb + ATT_K_OFF +
                      (uint32_t)((j2 * 16 + b_r) * AQ_STRB + (ks16 * 16 + b_k) * 2));
                mma16816(sc[2*j2],   aq, bk[0], bk[1]);
                mma16816(sc[2*j2+1], aq, bk[2], bk[3]);
            }
        }

        const float w0 = __expf(fminf(c0s[st] - gt0, 80.f));
        const float w1 = __expf(fminf(c0s[st] - gt1, 80.f));
        const bool diag = (st == nst - 1);
        const int tg0 = t0 + r0, tg1 = t0 + r1;
        uint32_t pa[8][2];
        #pragma unroll
        for (int j = 0; j < 8; j++) {
            int cb = s0 + j * 8 + 2 * (lane & 3);
            float wc0 = wcol[cb];
            float wc1 = wcol[cb + 1];
            float v00 = sc[j][0] * wc0 * w0, v01 = sc[j][1] * wc1 * w0;
            float v10 = sc[j][2] * wc0 * w1, v11 = sc[j][3] * wc1 * w1;
            if (diag) {
                if (cb     > tg0) v00 = 0.f;
                if (cb + 1 > tg0) v01 = 0.f;
                if (cb     > tg1) v10 = 0.f;
                if (cb + 1 > tg1) v11 = 0.f;
            }
            rsa0 += v00 + v01;
            rsa1 += v10 + v11;
            __half2 h0 = __floats2half2_rn(v00, v01);
            __half2 h1 = __floats2half2_rn(v10, v11);
            pa[j][0] = *(uint32_t*)&h0;
            pa[j][1] = *(uint32_t*)&h1;
        }

        #pragma unroll
        for (int kst = 0; kst < 4; kst++) {
            uint32_t af[4] = { pa[2*kst][0], pa[2*kst][1],
                               pa[2*kst+1][0], pa[2*kst+1][1] };
            #pragma unroll
            for (int n16 = 0; n16 < 16; n16++) {
                uint32_t bv[4];
                ldsm4t(bv, sb + ATT_V_OFF +
                       (uint32_t)((kst * 16 + v_k) * AV_STRB + (n16 * 16 + v_n) * 2));
                mma16816(acc[2*n16],   af, bv[0], bv[1]);
                mma16816(acc[2*n16+1], af, bv[2], bv[3]);
            }
        }
    }

    rsa0 += __shfl_xor_sync(0xffffffffu, rsa0, 1);
    rsa0 += __shfl_xor_sync(0xffffffffu, rsa0, 2);
    rsa1 += __shfl_xor_sync(0xffffffffu, rsa1, 1);
    rsa1 += __shfl_xor_sync(0xffffffffu, rsa1, 2);

    const float invn0 = 1.f / fmaxf(fabsf(rsa0), nfs[r0]);
    const float invn1 = 1.f / fmaxf(fabsf(rsa1), nfs[r1]);

    float sq0 = 0.f, sq1 = 0.f;
    #pragma unroll
    for (int f = 0; f < 32; f++) {
        float h00 = acc[f][0] * invn0, h01 = acc[f][1] * invn0;
        float h10 = acc[f][2] * invn1, h11 = acc[f][3] * invn1;
        sq0 += h00 * h00 + h01 * h01;
        sq1 += h10 * h10 + h11 * h11;
    }
    sq0 += __shfl_xor_sync(0xffffffffu, sq0, 1);
    sq0 += __shfl_xor_sync(0xffffffffu, sq0, 2);
    sq1 += __shfl_xor_sync(0xffffffffu, sq1, 1);
    sq1 += __shfl_xor_sync(0xffffffffu, sq1, 2);
    const float hs0 = rsqrtf(sq0 * (1.f / DVv) + 1e-6f) * invn0;
    const float hs1 = rsqrtf(sq1 * (1.f / DVv) + 1e-6f) * invn1;

    const __half* op0 = qkvo + (size_t)(bb * Sv + t0 + r0) * QKVO + 4096 + hh * DVv;
    const __half* op1 = qkvo + (size_t)(bb * Sv + t0 + r1) * QKVO + 4096 + hh * DVv;
    const float* mwv = mh_w + hh * DVv;
    __half* ho0 = houtp + ((size_t)(bb * Sv + t0 + r0)) * Dv + hh * DVv;
    __half* ho1 = houtp + ((size_t)(bb * Sv + t0 + r1)) * Dv + hh * DVv;
    #pragma unroll
    for (int f = 0; f < 32; f++) {
        int col = f * 8 + 2 * (lane & 3);
        float2 mw = *(const float2*)(mwv + col);
        __half2 oh0 = *(const __half2*)(op0 + col);
        __half2 oh1 = *(const __half2*)(op1 + col);
        float o0x = __half2float(__low2half(oh0)), o0y = __half2float(__high2half(oh0));
        float o1x = __half2float(__low2half(oh1)), o1y = __half2float(__high2half(oh1));
        float s00 = 1.f / (1.f + __expf(-o0x));
        float s01 = 1.f / (1.f + __expf(-o0y));
        float s10 = 1.f / (1.f + __expf(-o1x));
        float s11 = 1.f / (1.f + __expf(-o1y));
        float v00 = acc[f][0] * hs0 * mw.x * s00;
        float v01 = acc[f][1] * hs0 * mw.y * s01;
        float v10 = acc[f][2] * hs1 * mw.x * s10;
        float v11 = acc[f][3] * hs1 * mw.y * s11;
        *(__half2*)(ho0 + col) = __floats2half2_rn(v00, v01);
        *(__half2*)(ho1 + col) = __floats2half2_rn(v10, v11);
    }
}

// --------------------------- launch ----------------------------------------
extern "C" void kernel_launch(void* const* d_in, const int* in_sizes, int n_in,
                              void* d_out, int out_size)
{
    const float* x       = (const float*)d_in[0];
    const float* norm1_w = (const float*)d_in[1];
    const float* wq      = (const float*)d_in[2];
    const float* wk      = (const float*)d_in[3];
    const float* wv      = (const float*)d_in[4];
    const float* w_ig    = (const float*)d_in[5];
    const float* b_ig    = (const float*)d_in[6];
    const float* w_fg    = (const float*)d_in[7];
    const float* b_fg    = (const float*)d_in[8];
    const float* w_og    = (const float*)d_in[9];
    const float* mh_w    = (const float*)d_in[10];
    const float* w_out   = (const float*)d_in[11];
    const float* norm2_w = (const float*)d_in[12];
    const float* w_gate  = (const float*)d_in[13];
    const float* w_up    = (const float*)d_in[14];
    const float* w_down  = (const float*)d_in[15];
    float* out = (float*)d_out;

    void* fp = nullptr; cudaGetSymbolAddress(&fp, g_f32);
    void* hp = nullptr; cudaGetSymbolAddress(&hp, g_fp16);
    float* F = (float*)fp;
    __half* Hh = (__half*)hp;

    float *hin = F+F_HIN, *x1 = F+F_X1;
    float *ipre = F+F_IPRE, *fpre = F+F_FPRE, *ab = F+F_A, *Gb = F+F_G, *nfl = F+F_NFL;

    __half *hinP=Hh+P_HIN, *houtP=Hh+P_HOUT, *h2P=Hh+P_H2, *actP=Hh+P_ACT, *gateP=Hh+P_GATE;
    __half *partP=Hh+P_PART;
    __half *wqkvoH=Hh+P_WQ;     // contiguous [6144][2048]: wq|wk|wv|wog
    __half *wqh=Hh+P_WQ, *wkh=Hh+P_WK, *wvh=Hh+P_WV, *wogh=Hh+P_WOG;
    __half *wouth=Hh+P_WOUT, *wgh=Hh+P_WG, *wuh=Hh+P_WU, *wdh=Hh+P_WD;
    __half *qkvoP=Hh+P_QKVO;

    static cudaStream_t s1 = nullptr, s2 = nullptr;
    static cudaEvent_t evStart, evH, evW1, evW2, evScan, evD1, evRA;
    if (s1 == nullptr) {
        cudaStreamCreateWithFlags(&s1, cudaStreamNonBlocking);
        cudaStreamCreateWithFlags(&s2, cudaStreamNonBlocking);
        cudaEventCreateWithFlags(&evStart, cudaEventDisableTiming);
        cudaEventCreateWithFlags(&evH,     cudaEventDisableTiming);
        cudaEventCreateWithFlags(&evW1,    cudaEventDisableTiming);
        cudaEventCreateWithFlags(&evW2,    cudaEventDisableTiming);
        cudaEventCreateWithFlags(&evScan,  cudaEventDisableTiming);
        cudaEventCreateWithFlags(&evD1,    cudaEventDisableTiming);
        cudaEventCreateWithFlags(&evRA,    cudaEventDisableTiming);

        cudaFuncSetAttribute(attn_kernel, cudaFuncAttributeMaxDynamicSharedMemorySize, ATT_BYTES);
        cudaFuncSetAttribute(tgemm_kernel<0>, cudaFuncAttributeMaxDynamicSharedMemorySize, GSMEM);
        cudaFuncSetAttribute(tgemm_kernel<1>, cudaFuncAttributeMaxDynamicSharedMemorySize, GSMEM);
        cudaFuncSetAttribute(tgemm_kernel<3>, cudaFuncAttributeMaxDynamicSharedMemorySize, GSMEM);
        cudaFuncSetAttribute(tgemm_kernel<4>, cudaFuncAttributeMaxDynamicSharedMemorySize, GSMEM);
        cudaFuncSetAttribute(tgemm_kernel<6>, cudaFuncAttributeMaxDynamicSharedMemorySize, GSMEM);
    }

    dim3 tb(32, 8);

    cudaEventRecord(evStart, 0);
    cudaStreamWaitEvent(s1, evStart, 0);
    cudaStreamWaitEvent(s2, evStart, 0);

    // s1: weight transposes (projection weights first)
    wsplit_kernel<<<dim3(QKv/32, Dv/32), tb, 0, s1>>>(wq, wqh, Dv, QKv);
    wsplit_kernel<<<dim3(QKv/32, Dv/32), tb, 0, s1>>>(wk, wkh, Dv, QKv);
    wsplit_kernel<<<dim3(Dv/32,  Dv/32), tb, 0, s1>>>(wv, wvh, Dv, Dv);
    wsplit_kernel<<<dim3(Dv/32,  Dv/32), tb, 0, s1>>>(w_og, wogh, Dv, Dv);
    cudaEventRecord(evW1, s1);
    wsplit_kernel<<<dim3(Dv/32,  Dv/32), tb, 0, s1>>>(w_out, wouth, Dv, Dv);
    wsplit_kernel<<<dim3(FFv/32, Dv/32), tb, 0, s1>>>(w_gate, wgh, Dv, FFv);
    wsplit_kernel<<<dim3(FFv/32, Dv/32), tb, 0, s1>>>(w_up, wuh, Dv, FFv);
    wsplit_kernel<<<dim3(Dv/32, FFv/32), tb, 0, s1>>>(w_down, wdh, FFv, Dv);
    cudaEventRecord(evW2, s1);

    // s0: pre-norm 1
    rmsnorm_kernel<1><<<Mv, 256>>>(x, norm1_w, hin, hinP);
    cudaEventRecord(evH, 0);

    // s2: gates + scans (overlap with merged projection GEMM)
    cudaStreamWaitEvent(s2, evH, 0);
    gates_kernel<<<Mv, 256, 0, s2>>>(hin, w_ig, b_ig, w_fg, b_fg, ipre, fpre);
    scan_kernel<<<BHv, 1024, 0, s2>>>(ipre, fpre, ab, Gb, nfl);
    cudaEventRecord(evScan, s2);

    // s0: ONE merged projection GEMM  [4096 x 6144 x 2048] -> q|k|v|og fp16
    cudaStreamWaitEvent(0, evW1, 0);
    tgemm_kernel<3><<<dim3(QKVO/128, Mv/256), 256, GSMEM>>>(hinP, wqkvoH, nullptr, nullptr, nullptr, qkvoP, QKVO, Dv);

    // s0: attention + fused head-norm
    cudaStreamWaitEvent(0, evScan, 0);
    attn_kernel<<<dim3(Sv/64, BHv), 128, ATT_BYTES>>>(qkvoP, ab, Gb, nfl, mh_w, houtP);

    cudaStreamWaitEvent(0, evW2, 0);
    tgemm_kernel<1><<<dim3(Dv/128, Mv/256), 256, GSMEM>>>(houtP, wouth, x, nullptr, x1, nullptr, Dv, Dv);

    rmsnorm_kernel<0><<<Mv, 256>>>(x1, norm2_w, nullptr, h2P);

    tgemm_kernel<3><<<dim3(FFv/128, Mv/256), 256, GSMEM>>>(h2P, wgh, nullptr, nullptr, nullptr, gateP, FFv, Dv);
    tgemm_kernel<4><<<dim3(FFv/128, Mv/256), 256, GSMEM>>>(h2P, wuh, nullptr, gateP, nullptr, actP, FFv, Dv);

    // split-K=4 down-projection, N-split in two halves so the reducer of
    // half A (s1) overlaps the GEMM of half B (s0).
    tgemm_kernel<6><<<dim3(Dv/256, Mv/256, KSPL), 256, GSMEM>>>(actP, wdh, nullptr, nullptr, nullptr, partP, Dv, FFv);
    cudaEventRecord(evD1, 0);
    cudaStreamWaitEvent(s1, evD1, 0);
    addredh_kernel<<<Mv, 256, 0, s1>>>(x1, partP, out, 0);
    cudaEventRecord(evRA, s1);

    tgemm_kernel<6><<<dim3(Dv/256, Mv/256, KSPL), 256, GSMEM>>>(actP, wdh + (size_t)(Dv/2) * FFv, nullptr, nullptr, nullptr, partP + Dv/2, Dv, FFv);
    addredh_kernel<<<Mv, 256>>>(x1, partP, out, Dv/2);
    cudaStreamWaitEvent(0, evRA, 0);

    (void)in_sizes; (void)n_in; (void)out_size;
}

// round 16
// speedup vs baseline: 1.0264x; 1.0264x over previous
#include <cuda_runtime.h>
#include <cuda_fp16.h>
#include <math.h>
#include <stdint.h>

// ---------------------------------------------------------------------------
// BolmoLocalLayer: xLSTM mixer + SwiGLU MLP.  B=2, S=2048, D=2048, H=8.
// Round 16: revert to R14 (measured best, 1884 us).  Single full-width
// split-K=4 down-projection with fp16 partials; merged qkvo GEMM; fused
// headnorm attention; NSTG=3 pipelines; three-stream schedule.
// ---------------------------------------------------------------------------

#define Bv   2
#define Sv   2048
#define Dv   2048
#define Hv   8
#define QKv  1024
#define DQK  128
#define DVv  256
#define FFv  8192
#define Mv   (Bv*Sv)      // 4096
#define BHv  (Bv*Hv)      // 16
#define QKVO 6144         // merged projection width: q(1024)|k(1024)|v(2048)|og(2048)
#define KSPL 4            // down-proj split-K factor

// ----------------------------- fp32 scratch --------------------------------
#define F_HIN   ((size_t)0)
#define F_X1    (F_HIN  + (size_t)Mv*Dv)
#define F_IPRE  (F_X1   + (size_t)Mv*Dv)
#define F_FPRE  (F_IPRE + (size_t)BHv*Sv)
#define F_A     (F_FPRE + (size_t)BHv*Sv)
#define F_G     (F_A    + (size_t)BHv*Sv)
#define F_NFL   (F_G    + (size_t)BHv*Sv)
#define F_TOTAL (F_NFL  + (size_t)BHv*Sv)
__device__ __align__(256) float g_f32[F_TOTAL];

// ----------------------------- fp16 scratch --------------------------------
#define P_HIN   ((size_t)0)
#define P_HOUT  (P_HIN   + (size_t)Mv*Dv)
#define P_H2    (P_HOUT  + (size_t)Mv*Dv)
#define P_ACT   (P_H2    + (size_t)Mv*Dv)
#define P_GATE  (P_ACT   + (size_t)Mv*FFv)
#define P_PART  (P_GATE  + (size_t)Mv*FFv)
#define P_WQ    (P_PART  + (size_t)KSPL*Mv*Dv)
#define P_WK    (P_WQ    + (size_t)QKv*Dv)
#define P_WV    (P_WK    + (size_t)QKv*Dv)
#define P_WOG   (P_WV    + (size_t)Dv*Dv)
#define P_WOUT  (P_WOG   + (size_t)Dv*Dv)
#define P_WG    (P_WOUT  + (size_t)Dv*Dv)
#define P_WU    (P_WG    + (size_t)FFv*Dv)
#define P_WD    (P_WU    + (size_t)FFv*Dv)
#define P_QKVO  (P_WD    + (size_t)Dv*FFv)
#define P_TOTAL (P_QKVO  + (size_t)Mv*QKVO)
__device__ __align__(256) __half g_fp16[P_TOTAL];

// ----------------------------- helpers -------------------------------------
__device__ __forceinline__ uint32_t smem_u32(const void* p) {
    uint32_t a;
    asm("{ .reg .u64 t; cvta.to.shared.u64 t, %1; cvt.u32.u64 %0, t; }"
        : "=r"(a) : "l"(p));
    return a;
}

__device__ __forceinline__ void cp16(uint32_t sa, const void* g) {
    asm volatile("cp.async.ca.shared.global [%0], [%1], 16;"
                 :: "r"(sa), "l"(g) : "memory");
}
#define CP_COMMIT() asm volatile("cp.async.commit_group;" ::: "memory")
#define CP_WAIT1()  asm volatile("cp.async.wait_group 1;" ::: "memory")
#define CP_WAIT0()  asm volatile("cp.async.wait_group 0;" ::: "memory")

__device__ __forceinline__ void ldsm4(uint32_t* r, uint32_t addr) {
    asm volatile("ldmatrix.sync.aligned.m8n8.x4.shared.b16 {%0,%1,%2,%3}, [%4];"
                 : "=r"(r[0]), "=r"(r[1]), "=r"(r[2]), "=r"(r[3]) : "r"(addr));
}
__device__ __forceinline__ void ldsm4t(uint32_t* r, uint32_t addr) {
    asm volatile("ldmatrix.sync.aligned.m8n8.x4.trans.shared.b16 {%0,%1,%2,%3}, [%4];"
                 : "=r"(r[0]), "=r"(r[1]), "=r"(r[2]), "=r"(r[3]) : "r"(addr));
}

__device__ __forceinline__ void mma16816(float* c, const uint32_t* a,
                                         uint32_t b0, uint32_t b1) {
    asm volatile(
        "mma.sync.aligned.m16n8k16.row.col.f32.f16.f16.f32 "
        "{%0,%1,%2,%3}, {%4,%5,%6,%7}, {%8,%9}, {%0,%1,%2,%3};"
        : "+f"(c[0]), "+f"(c[1]), "+f"(c[2]), "+f"(c[3])
        : "r"(a[0]), "r"(a[1]), "r"(a[2]), "r"(a[3]), "r"(b0), "r"(b1));
}

// --------------------------- HMMA GEMM (1-pass fp16) ------------------------
// CTA tile 256x128, warp tile 64x64.  3-stage cp.async pipeline.
// EPI 0: C fp32 = acc.        EPI 1: C fp32 = aux + acc.
// EPI 3: CH fp16 = acc.       EPI 4: CH fp16 = silu(auxh) * acc.
// EPI 6: split-K partial fp16 — plane z (blockIdx.z), K-slice of K/KSPL.
#define KCH    64
#define RSTRB  144
#define ATILEB (256*RSTRB)
#define BTILEB (128*RSTRB)
#define NSTG   3
#define STAGEB (ATILEB + BTILEB)        // 55296
#define GSMEM  (NSTG*STAGEB)            // 165888

template<int EPI>
__global__ void __launch_bounds__(256) tgemm_kernel(
    const __half* __restrict__ AH, const __half* __restrict__ BH,
    const float* __restrict__ aux, const __half* __restrict__ auxh,
    float* __restrict__ C, __half* __restrict__ CH, int N, int K)
{
    extern __shared__ char smem[];
    const uint32_t sb = smem_u32(smem);
    const int tid = threadIdx.x;
    const int lane = tid & 31;
    const int wid = tid >> 5;
    const int wm = wid & 3;
    const int wn = wid >> 2;
    const int m0 = blockIdx.y * 256;
    const int n0 = blockIdx.x * 128;

    const int kslice = (EPI == 6) ? (K / KSPL) : K;
    const int koff   = (EPI == 6) ? ((int)blockIdx.z * kslice) : 0;

    const __half* srcA = AH + (size_t)m0 * K + koff;
    const __half* srcB = BH + (size_t)n0 * K + koff;

    float acc[4][8][4];
    #pragma unroll
    for (int i = 0; i < 4; i++)
        #pragma unroll
        for (int j = 0; j < 8; j++)
            #pragma unroll
            for (int e = 0; e < 4; e++) acc[i][j][e] = 0.f;

    const int NC = kslice / KCH;

    auto load_chunk = [&](int c, int s) {
        const __half* ga = srcA + c * KCH;
        uint32_t abase = sb + (uint32_t)(s * STAGEB);
        #pragma unroll
        for (int i = 0; i < 8; i++) {
            int seg = tid + 256 * i;
            int row = seg >> 3, s8 = seg & 7;
            cp16(abase + (uint32_t)(row * RSTRB + s8 * 16),
                 ga + (size_t)row * K + s8 * 8);
        }
        const __half* gb = srcB + c * KCH;
        uint32_t bbase = abase + ATILEB;
        #pragma unroll
        for (int i = 0; i < 4; i++) {
            int seg = tid + 256 * i;
            int row = seg >> 3, s8 = seg & 7;
            cp16(bbase + (uint32_t)(row * RSTRB + s8 * 16),
                 gb + (size_t)row * K + s8 * 8);
        }
    };

    load_chunk(0, 0); CP_COMMIT();
    load_chunk(1, 1); CP_COMMIT();

    const int a_r = (lane & 15);
    const int a_k = (lane >> 4) * 8;
    const int b_r = (lane & 7) + (lane >> 4) * 8;
    const int b_k = ((lane >> 3) & 1) * 8;

    for (int c = 0; c < NC; c++) {
        const int s = c % NSTG;
        if (c + 1 < NC) CP_WAIT1(); else CP_WAIT0();
        __syncthreads();
        if (c + 2 < NC) { load_chunk(c + 2, (c + 2) % NSTG); CP_COMMIT(); }

        const uint32_t bA = sb + s * STAGEB;
        const uint32_t bB = bA + ATILEB;

        #pragma unroll
        for (int kk = 0; kk < KCH; kk += 16) {
            uint32_t aH[4][4], bf[4][4];
            #pragma unroll
            for (int mt = 0; mt < 4; mt++) {
                int row = wm * 64 + mt * 16 + a_r;
                ldsm4(aH[mt], bA + (uint32_t)(row * RSTRB + (kk + a_k) * 2));
            }
            #pragma unroll
            for (int j = 0; j < 4; j++) {
                int row = wn * 64 + j * 16 + b_r;
                ldsm4(bf[j], bB + (uint32_t)(row * RSTRB + (kk + b_k) * 2));
            }
            #pragma unroll
            for (int mt = 0; mt < 4; mt++)
                #pragma unroll
                for (int j = 0; j < 4; j++) {
                    mma16816(acc[mt][2*j],   aH[mt], bf[j][0], bf[j][1]);
                    mma16816(acc[mt][2*j+1], aH[mt], bf[j][2], bf[j][3]);
                }
        }
    }

    __half* CHbase = CH;
    if (EPI == 6) CHbase = CH + (size_t)blockIdx.z * Mv * Dv;

    const int mrow = m0 + wm * 64;
    const int ncol = n0 + wn * 64;
    #pragma unroll
    for (int mt = 0; mt < 4; mt++) {
        #pragma unroll
        for (int nt = 0; nt < 8; nt++) {
            int r0 = mrow + mt * 16 + (lane >> 2);
            int r1 = r0 + 8;
            int cc = ncol + nt * 8 + (lane & 3) * 2;
            float* a = acc[mt][nt];
            size_t i0 = (size_t)r0 * N + cc;
            size_t i1 = (size_t)r1 * N + cc;
            if (EPI == 0) {
                *(float2*)(C + i0) = make_float2(a[0], a[1]);
                *(float2*)(C + i1) = make_float2(a[2], a[3]);
            } else if (EPI == 1) {
                float2 x0 = *(const float2*)(aux + i0);
                float2 x1 = *(const float2*)(aux + i1);
                *(float2*)(C + i0) = make_float2(a[0] + x0.x, a[1] + x0.y);
                *(float2*)(C + i1) = make_float2(a[2] + x1.x, a[3] + x1.y);
            } else if (EPI == 4) {
                __half2 gh0 = *(const __half2*)(auxh + i0);
                __half2 gh1 = *(const __half2*)(auxh + i1);
                float g0x = __half2float(__low2half(gh0)), g0y = __half2float(__high2half(gh0));
                float g1x = __half2float(__low2half(gh1)), g1y = __half2float(__high2half(gh1));
                float v00 = a[0] * (g0x / (1.f + __expf(-g0x)));
                float v01 = a[1] * (g0y / (1.f + __expf(-g0y)));
                float v10 = a[2] * (g1x / (1.f + __expf(-g1x)));
                float v11 = a[3] * (g1y / (1.f + __expf(-g1y)));
                *(__half2*)(CH + i0) = __floats2half2_rn(v00, v01);
                *(__half2*)(CH + i1) = __floats2half2_rn(v10, v11);
            } else {   // EPI 3 or 6: plain fp16 store
                *(__half2*)(CHbase + i0) = __floats2half2_rn(a[0], a[1]);
                *(__half2*)(CHbase + i1) = __floats2half2_rn(a[2], a[3]);
            }
        }
    }
}

// ---------------- split-K reduce: out = x1 + sum(fp16 partials) -------------
__global__ void addred_kernel(const float* __restrict__ x1,
                              const __half* __restrict__ P,
                              float* __restrict__ out)
{
    size_t i = ((size_t)blockIdx.x * 256 + threadIdx.x) * 4;
    float4 r = *(const float4*)(x1 + i);
    #pragma unroll
    for (int z = 0; z < KSPL; z++) {
        const __half2* p2 = (const __half2*)(P + (size_t)z * Mv * Dv + i);
        __half2 a = p2[0], b = p2[1];
        r.x += __half2float(__low2half(a));
        r.y += __half2float(__high2half(a));
        r.z += __half2float(__low2half(b));
        r.w += __half2float(__high2half(b));
    }
    *(float4*)(out + i) = r;
}

// ---------------- weight transpose -> fp16 ---------------------------------
__global__ void wsplit_kernel(const float* __restrict__ W,
                              __half* __restrict__ TH, int K, int N)
{
    __shared__ float t[32][33];
    int tx = threadIdx.x, ty = threadIdx.y;
    int n0 = blockIdx.x * 32, k0 = blockIdx.y * 32;
    #pragma unroll
    for (int j = 0; j < 4; j++)
        t[ty + 8 * j][tx] = W[(size_t)(k0 + ty + 8 * j) * N + n0 + tx];
    __syncthreads();
    #pragma unroll
    for (int j = 0; j < 4; j++) {
        float v = t[tx][ty + 8 * j];
        TH[(size_t)(n0 + ty + 8 * j) * K + k0 + tx] = __float2half_rn(v);
    }
}

// --------------------------- RMSNorm (-> fp16, optional fp32) ---------------
template<int WRITE_F32>
__global__ void rmsnorm_kernel(const float* __restrict__ x, const float* __restrict__ w,
                               float* __restrict__ out, __half* __restrict__ oh)
{
    int row = blockIdx.x;
    int tid = threadIdx.x;
    const float4* xr = (const float4*)(x + (size_t)row * Dv);
    float4 v0 = xr[tid];
    float4 v1 = xr[tid + 256];
    float ss = v0.x*v0.x + v0.y*v0.y + v0.z*v0.z + v0.w*v0.w
             + v1.x*v1.x + v1.y*v1.y + v1.z*v1.z + v1.w*v1.w;
    #pragma unroll
    for (int o = 16; o > 0; o >>= 1) ss += __shfl_xor_sync(0xffffffffu, ss, o);
    __shared__ float red[8];
    int wp = tid >> 5, lane = tid & 31;
    if (lane == 0) red[wp] = ss;
    __syncthreads();
    float tot = 0.f;
    #pragma unroll
    for (int i = 0; i < 8; i++) tot += red[i];
    float inv = rsqrtf(tot * (1.f / Dv) + 1e-6f);
    const float4* wr = (const float4*)w;
    #pragma unroll
    for (int half_ = 0; half_ < 2; half_++) {
        float4 v = half_ ? v1 : v0;
        float4 ww = wr[tid + 256 * half_];
        float r[4] = { v.x*inv*ww.x, v.y*inv*ww.y, v.z*inv*ww.z, v.w*inv*ww.w };
        size_t idx = (size_t)row * Dv + (tid + 256 * half_) * 4;
        if (WRITE_F32) *(float4*)(out + idx) = make_float4(r[0], r[1], r[2], r[3]);
        __half2 h0 = __floats2half2_rn(r[0], r[1]);
        __half2 h1 = __floats2half2_rn(r[2], r[3]);
        *(__half2*)(oh + idx) = h0;
        *(__half2*)(oh + idx + 2) = h1;
    }
}

// --------------------------- i/f gate projections ---------------------------
__device__ __forceinline__ float softcap15(float x) {
    return 15.f * tanhf(x * (1.f / 15.f));
}

__global__ void gates_kernel(const float* __restrict__ hin,
                             const float* __restrict__ w_ig, const float* __restrict__ b_ig,
                             const float* __restrict__ w_fg, const float* __restrict__ b_fg,
                             float* __restrict__ ipre, float* __restrict__ fpre)
{
    int row = blockIdx.x;
    int tid = threadIdx.x;
    float pi[8], pf[8];
    #pragma unroll
    for (int h = 0; h < 8; h++) { pi[h] = 0.f; pf[h] = 0.f; }
    const float* xr = hin + (size_t)row * Dv;
    for (int d = tid; d < Dv; d += 256) {
        float xv = xr[d];
        #pragma unroll
        for (int h = 0; h < 8; h++) {
            pi[h] += xv * w_ig[d * 8 + h];
            pf[h] += xv * w_fg[d * 8 + h];
        }
    }
    #pragma unroll
    for (int h = 0; h < 8; h++) {
        #pragma unroll
        for (int o = 16; o > 0; o >>= 1) {
            pi[h] += __shfl_xor_sync(0xffffffffu, pi[h], o);
            pf[h] += __shfl_xor_sync(0xffffffffu, pf[h], o);
        }
    }
    __shared__ float sred[8][16];
    int wp = tid >> 5, lane = tid & 31;
    if (lane == 0) {
        #pragma unroll
        for (int h = 0; h < 8; h++) { sred[wp][h] = pi[h]; sred[wp][8 + h] = pf[h]; }
    }
    __syncthreads();
    if (tid < 16) {
        float s = 0.f;
        #pragma unroll
        for (int w8 = 0; w8 < 8; w8++) s += sred[w8][tid];
        int h = tid & 7;
        bool isf = (tid >= 8);
        float bias = isf ? b_fg[h] : b_ig[h];
        float val = softcap15(s + bias);
        int b = row >> 11;
        int sp = row & (Sv - 1);
        int bh = b * Hv + h;
        (isf ? fpre : ipre)[bh * Sv + sp] = val;
    }
}

// --------------------------- gate scans ------------------------------------
__global__ void scan_kernel(const float* __restrict__ ipre, const float* __restrict__ fpre,
                            float* __restrict__ aout, float* __restrict__ Gout,
                            float* __restrict__ nflout)
{
    int bh = blockIdx.x;
    int tid = threadIdx.x;
    __shared__ float bufA[2048], bufB[2048], fc[2048];

    for (int i = tid; i < 2048; i += 1024) {
        float f = fpre[bh * Sv + i];
        bufA[i] = fminf(f, 0.f) - log1pf(expf(-fabsf(f)));
    }
    __syncthreads();
    float* src = bufA; float* dst = bufB;
    for (int off = 1; off < 2048; off <<= 1) {
        for (int i = tid; i < 2048; i += 1024)
            dst[i] = src[i] + ((i >= off) ? src[i - off] : 0.f);
        __syncthreads();
        float* t = src; src = dst; dst = t;
    }
    for (int i = tid; i < 2048; i += 1024) fc[i] = src[i];
    __syncthreads();
    for (int i = tid; i < 2048; i += 1024) {
        float a = ipre[bh * Sv + i] - fc[i];
        aout[bh * Sv + i] = a;
        dst[i] = a;
    }
    __syncthreads();
    { float* t = src; src = dst; dst = t; }
    for (int off = 1; off < 2048; off <<= 1) {
        for (int i = tid; i < 2048; i += 1024)
            dst[i] = fmaxf(src[i], (i >= off) ? src[i - off] : -1e30f);
        __syncthreads();
        float* t = src; src = dst; dst = t;
    }
    for (int i = tid; i < 2048; i += 1024) {
        float G = src[i];
        Gout[bh * Sv + i] = G;
        nflout[bh * Sv + i] = expf(-(fc[i] + G));
    }
}

// ------------------ HMMA mLSTM attention + fused head-norm ------------------
#define AQ_STRB 272
#define AV_STRB 528
#define ATT_Q_OFF   0
#define ATT_K_OFF   (64*AQ_STRB)
#define ATT_V_OFF   (ATT_K_OFF + 64*AQ_STRB)
#define ATT_WCOL    (ATT_V_OFF + 64*AV_STRB)
#define ATT_C0      (ATT_WCOL + 2048*4)
#define ATT_GT      (ATT_C0 + 32*4)
#define ATT_NF      (ATT_GT + 64*4)
#define ATT_BYTES   (ATT_NF + 64*4)

__global__ void __launch_bounds__(128, 2) attn_kernel(
    const __half* __restrict__ qkvo,
    const float* __restrict__ av, const float* __restrict__ Gv,
    const float* __restrict__ nfv, const float* __restrict__ mh_w,
    __half* __restrict__ houtp)
{
    extern __shared__ char smem[];
    const uint32_t sb = smem_u32(smem);
    float* wcol = (float*)(smem + ATT_WCOL);
    float* c0s  = (float*)(smem + ATT_C0);
    float* gts  = (float*)(smem + ATT_GT);
    float* nfs  = (float*)(smem + ATT_NF);

    const int bh = blockIdx.y;
    const int bb = bh >> 3, hh = bh & 7;
    const int t0 = ((int)gridDim.x - 1 - (int)blockIdx.x) * 64;
    const int tid = threadIdx.x, lane = tid & 31, wid = tid >> 5;
    const int nst = (t0 >> 6) + 1;
    const int nS = t0 + 64;

    const __half* qbase = qkvo + (size_t)(bb * Sv + t0) * QKVO + hh * DQK;
    #pragma unroll
    for (int i = 0; i < 8; i++) {
        int seg = tid + 128 * i;
        int row = seg >> 4, s16 = seg & 15;
        cp16(sb + ATT_Q_OFF + (uint32_t)(row * AQ_STRB + s16 * 16),
             qbase + (size_t)row * QKVO + s16 * 8);
    }
    CP_COMMIT();

    for (int s = tid; s < nS; s += 128) wcol[s] = av[(size_t)bh * Sv + s];
    if (tid < 64) {
        gts[tid] = Gv[(size_t)bh * Sv + t0 + tid];
        nfs[tid] = nfv[(size_t)bh * Sv + t0 + tid];
    }
    __syncthreads();
    if (tid < nst) {
        float m = -1e30f;
        #pragma unroll 8
        for (int i = 0; i < 64; i++) m = fmaxf(m, wcol[tid * 64 + i]);
        c0s[tid] = m;
    }
    __syncthreads();
    const float invsq = 0.08838834764831845f;
    for (int s = tid; s < nS; s += 128)
        wcol[s] = __expf(wcol[s] - c0s[s >> 6]) * invsq;
    __syncthreads();

    const int qr = lane >> 2;
    const int r0 = wid * 16 + qr, r1 = r0 + 8;
    const float gt0 = gts[r0], gt1 = gts[r1];

    const int a_r = lane & 15, a_k = (lane >> 4) * 8;
    const int b_r = (lane & 7) + (lane >> 4) * 8;
    const int b_k = ((lane >> 3) & 1) * 8;
    const int v_k = (lane & 7) + ((lane >> 3) & 1) * 8;
    const int v_n = (lane >> 4) * 8;

    float acc[32][4];
    #pragma unroll
    for (int f = 0; f < 32; f++)
        #pragma unroll
        for (int e = 0; e < 4; e++) acc[f][e] = 0.f;
    float rsa0 = 0.f, rsa1 = 0.f;

    for (int st = 0; st < nst; st++) {
        const int s0 = st << 6;
        __syncthreads();
        const __half* kbase = qkvo + (size_t)(bb * Sv + s0) * QKVO + QKv + hh * DQK;
        #pragma unroll
        for (int i = 0; i < 8; i++) {
            int seg = tid + 128 * i;
            int row = seg >> 4, s16 = seg & 15;
            cp16(sb + ATT_K_OFF + (uint32_t)(row * AQ_STRB + s16 * 16),
                 kbase + (size_t)row * QKVO + s16 * 8);
        }
        const __half* vbase = qkvo + (size_t)(bb * Sv + s0) * QKVO + 2 * QKv + hh * DVv;
        #pragma unroll
        for (int i = 0; i < 16; i++) {
            int seg = tid + 128 * i;
            int row = seg >> 5, s16 = seg & 31;
            cp16(sb + ATT_V_OFF + (uint32_t)(row * AV_STRB + s16 * 16),
                 vbase + (size_t)row * QKVO + s16 * 8);
        }
        CP_COMMIT(); CP_WAIT0();
        __syncthreads();

        float sc[8][4];
        #pragma unroll
        for (int j = 0; j < 8; j++)
            #pragma unroll
            for (int e = 0; e < 4; e++) sc[j][e] = 0.f;
        #pragma unroll
        for (int ks16 = 0; ks16 < 8; ks16++) {
            uint32_t aq[4];
            ldsm4(aq, sb + ATT_Q_OFF +
                  (uint32_t)((wid * 16 + a_r) * AQ_STRB + (ks16 * 16 + a_k) * 2));
            #pragma unroll
            for (int j2 = 0; j2 < 4; j2++) {
                uint32_t bk[4];
                ldsm4(bk, sb + ATT_K_OFF +
                      (uint32_t)((j2 * 16 + b_r) * AQ_STRB + (ks16 * 16 + b_k) * 2));
                mma16816(sc[2*j2],   aq, bk[0], bk[1]);
                mma16816(sc[2*j2+1], aq, bk[2], bk[3]);
            }
        }

        const float w0 = __expf(fminf(c0s[st] - gt0, 80.f));
        const float w1 = __expf(fminf(c0s[st] - gt1, 80.f));
        const bool diag = (st == nst - 1);
        const int tg0 = t0 + r0, tg1 = t0 + r1;
        uint32_t pa[8][2];
        #pragma unroll
        for (int j = 0; j < 8; j++) {
            int cb = s0 + j * 8 + 2 * (lane & 3);
            float wc0 = wcol[cb];
            float wc1 = wcol[cb + 1];
            float v00 = sc[j][0] * wc0 * w0, v01 = sc[j][1] * wc1 * w0;
            float v10 = sc[j][2] * wc0 * w1, v11 = sc[j][3] * wc1 * w1;
            if (diag) {
                if (cb     > tg0) v00 = 0.f;
                if (cb + 1 > tg0) v01 = 0.f;
                if (cb     > tg1) v10 = 0.f;
                if (cb + 1 > tg1) v11 = 0.f;
            }
            rsa0 += v00 + v01;
            rsa1 += v10 + v11;
            __half2 h0 = __floats2half2_rn(v00, v01);
            __half2 h1 = __floats2half2_rn(v10, v11);
            pa[j][0] = *(uint32_t*)&h0;
            pa[j][1] = *(uint32_t*)&h1;
        }

        #pragma unroll
        for (int kst = 0; kst < 4; kst++) {
            uint32_t af[4] = { pa[2*kst][0], pa[2*kst][1],
                               pa[2*kst+1][0], pa[2*kst+1][1] };
            #pragma unroll
            for (int n16 = 0; n16 < 16; n16++) {
                uint32_t bv[4];
                ldsm4t(bv, sb + ATT_V_OFF +
                       (uint32_t)((kst * 16 + v_k) * AV_STRB + (n16 * 16 + v_n) * 2));
                mma16816(acc[2*n16],   af, bv[0], bv[1]);
                mma16816(acc[2*n16+1], af, bv[2], bv[3]);
            }
        }
    }

    rsa0 += __shfl_xor_sync(0xffffffffu, rsa0, 1);
    rsa0 += __shfl_xor_sync(0xffffffffu, rsa0, 2);
    rsa1 += __shfl_xor_sync(0xffffffffu, rsa1, 1);
    rsa1 += __shfl_xor_sync(0xffffffffu, rsa1, 2);

    const float invn0 = 1.f / fmaxf(fabsf(rsa0), nfs[r0]);
    const float invn1 = 1.f / fmaxf(fabsf(rsa1), nfs[r1]);

    float sq0 = 0.f, sq1 = 0.f;
    #pragma unroll
    for (int f = 0; f < 32; f++) {
        float h00 = acc[f][0] * invn0, h01 = acc[f][1] * invn0;
        float h10 = acc[f][2] * invn1, h11 = acc[f][3] * invn1;
        sq0 += h00 * h00 + h01 * h01;
        sq1 += h10 * h10 + h11 * h11;
    }
    sq0 += __shfl_xor_sync(0xffffffffu, sq0, 1);
    sq0 += __shfl_xor_sync(0xffffffffu, sq0, 2);
    sq1 += __shfl_xor_sync(0xffffffffu, sq1, 1);
    sq1 += __shfl_xor_sync(0xffffffffu, sq1, 2);
    const float hs0 = rsqrtf(sq0 * (1.f / DVv) + 1e-6f) * invn0;
    const float hs1 = rsqrtf(sq1 * (1.f / DVv) + 1e-6f) * invn1;

    const __half* op0 = qkvo + (size_t)(bb * Sv + t0 + r0) * QKVO + 4096 + hh * DVv;
    const __half* op1 = qkvo + (size_t)(bb * Sv + t0 + r1) * QKVO + 4096 + hh * DVv;
    const float* mwv = mh_w + hh * DVv;
    __half* ho0 = houtp + ((size_t)(bb * Sv + t0 + r0)) * Dv + hh * DVv;
    __half* ho1 = houtp + ((size_t)(bb * Sv + t0 + r1)) * Dv + hh * DVv;
    #pragma unroll
    for (int f = 0; f < 32; f++) {
        int col = f * 8 + 2 * (lane & 3);
        float2 mw = *(const float2*)(mwv + col);
        __half2 oh0 = *(const __half2*)(op0 + col);
        __half2 oh1 = *(const __half2*)(op1 + col);
        float o0x = __half2float(__low2half(oh0)), o0y = __half2float(__high2half(oh0));
        float o1x = __half2float(__low2half(oh1)), o1y = __half2float(__high2half(oh1));
        float s00 = 1.f / (1.f + __expf(-o0x));
        float s01 = 1.f / (1.f + __expf(-o0y));
        float s10 = 1.f / (1.f + __expf(-o1x));
        float s11 = 1.f / (1.f + __expf(-o1y));
        float v00 = acc[f][0] * hs0 * mw.x * s00;
        float v01 = acc[f][1] * hs0 * mw.y * s01;
        float v10 = acc[f][2] * hs1 * mw.x * s10;
        float v11 = acc[f][3] * hs1 * mw.y * s11;
        *(__half2*)(ho0 + col) = __floats2half2_rn(v00, v01);
        *(__half2*)(ho1 + col) = __floats2half2_rn(v10, v11);
    }
}

// --------------------------- launch ----------------------------------------
extern "C" void kernel_launch(void* const* d_in, const int* in_sizes, int n_in,
                              void* d_out, int out_size)
{
    const float* x       = (const float*)d_in[0];
    const float* norm1_w = (const float*)d_in[1];
    const float* wq      = (const float*)d_in[2];
    const float* wk      = (const float*)d_in[3];
    const float* wv      = (const float*)d_in[4];
    const float* w_ig    = (const float*)d_in[5];
    const float* b_ig    = (const float*)d_in[6];
    const float* w_fg    = (const float*)d_in[7];
    const float* b_fg    = (const float*)d_in[8];
    const float* w_og    = (const float*)d_in[9];
    const float* mh_w    = (const float*)d_in[10];
    const float* w_out   = (const float*)d_in[11];
    const float* norm2_w = (const float*)d_in[12];
    const float* w_gate  = (const float*)d_in[13];
    const float* w_up    = (const float*)d_in[14];
    const float* w_down  = (const float*)d_in[15];
    float* out = (float*)d_out;

    void* fp = nullptr; cudaGetSymbolAddress(&fp, g_f32);
    void* hp = nullptr; cudaGetSymbolAddress(&hp, g_fp16);
    float* F = (float*)fp;
    __half* Hh = (__half*)hp;

    float *hin = F+F_HIN, *x1 = F+F_X1;
    float *ipre = F+F_IPRE, *fpre = F+F_FPRE, *ab = F+F_A, *Gb = F+F_G, *nfl = F+F_NFL;

    __half *hinP=Hh+P_HIN, *houtP=Hh+P_HOUT, *h2P=Hh+P_H2, *actP=Hh+P_ACT, *gateP=Hh+P_GATE;
    __half *partP=Hh+P_PART;
    __half *wqkvoH=Hh+P_WQ;     // contiguous [6144][2048]: wq|wk|wv|wog
    __half *wqh=Hh+P_WQ, *wkh=Hh+P_WK, *wvh=Hh+P_WV, *wogh=Hh+P_WOG;
    __half *wouth=Hh+P_WOUT, *wgh=Hh+P_WG, *wuh=Hh+P_WU, *wdh=Hh+P_WD;
    __half *qkvoP=Hh+P_QKVO;

    static cudaStream_t s1 = nullptr, s2 = nullptr;
    static cudaEvent_t evStart, evH, evW1, evW2, evScan;
    if (s1 == nullptr) {
        cudaStreamCreateWithFlags(&s1, cudaStreamNonBlocking);
        cudaStreamCreateWithFlags(&s2, cudaStreamNonBlocking);
        cudaEventCreateWithFlags(&evStart, cudaEventDisableTiming);
        cudaEventCreateWithFlags(&evH,     cudaEventDisableTiming);
        cudaEventCreateWithFlags(&evW1,    cudaEventDisableTiming);
        cudaEventCreateWithFlags(&evW2,    cudaEventDisableTiming);
        cudaEventCreateWithFlags(&evScan,  cudaEventDisableTiming);

        cudaFuncSetAttribute(attn_kernel, cudaFuncAttributeMaxDynamicSharedMemorySize, ATT_BYTES);
        cudaFuncSetAttribute(tgemm_kernel<0>, cudaFuncAttributeMaxDynamicSharedMemorySize, GSMEM);
        cudaFuncSetAttribute(tgemm_kernel<1>, cudaFuncAttributeMaxDynamicSharedMemorySize, GSMEM);
        cudaFuncSetAttribute(tgemm_kernel<3>, cudaFuncAttributeMaxDynamicSharedMemorySize, GSMEM);
        cudaFuncSetAttribute(tgemm_kernel<4>, cudaFuncAttributeMaxDynamicSharedMemorySize, GSMEM);
        cudaFuncSetAttribute(tgemm_kernel<6>, cudaFuncAttributeMaxDynamicSharedMemorySize, GSMEM);
    }

    dim3 tb(32, 8);

    cudaEventRecord(evStart, 0);
    cudaStreamWaitEvent(s1, evStart, 0);
    cudaStreamWaitEvent(s2, evStart, 0);

    // s1: weight transposes (projection weights first)
    wsplit_kernel<<<dim3(QKv/32, Dv/32), tb, 0, s1>>>(wq, wqh, Dv, QKv);
    wsplit_kernel<<<dim3(QKv/32, Dv/32), tb, 0, s1>>>(wk, wkh, Dv, QKv);
    wsplit_kernel<<<dim3(Dv/32,  Dv/32), tb, 0, s1>>>(wv, wvh, Dv, Dv);
    wsplit_kernel<<<dim3(Dv/32,  Dv/32), tb, 0, s1>>>(w_og, wogh, Dv, Dv);
    cudaEventRecord(evW1, s1);
    wsplit_kernel<<<dim3(Dv/32,  Dv/32), tb, 0, s1>>>(w_out, wouth, Dv, Dv);
    wsplit_kernel<<<dim3(FFv/32, Dv/32), tb, 0, s1>>>(w_gate, wgh, Dv, FFv);
    wsplit_kernel<<<dim3(FFv/32, Dv/32), tb, 0, s1>>>(w_up, wuh, Dv, FFv);
    wsplit_kernel<<<dim3(Dv/32, FFv/32), tb, 0, s1>>>(w_down, wdh, FFv, Dv);
    cudaEventRecord(evW2, s1);

    // s0: pre-norm 1
    rmsnorm_kernel<1><<<Mv, 256>>>(x, norm1_w, hin, hinP);
    cudaEventRecord(evH, 0);

    // s2: gates + scans (overlap with merged projection GEMM)
    cudaStreamWaitEvent(s2, evH, 0);
    gates_kernel<<<Mv, 256, 0, s2>>>(hin, w_ig, b_ig, w_fg, b_fg, ipre, fpre);
    scan_kernel<<<BHv, 1024, 0, s2>>>(ipre, fpre, ab, Gb, nfl);
    cudaEventRecord(evScan, s2);

    // s0: ONE merged projection GEMM  [4096 x 6144 x 2048] -> q|k|v|og fp16
    cudaStreamWaitEvent(0, evW1, 0);
    tgemm_kernel<3><<<dim3(QKVO/128, Mv/256), 256, GSMEM>>>(hinP, wqkvoH, nullptr, nullptr, nullptr, qkvoP, QKVO, Dv);

    // s0: attention + fused head-norm
    cudaStreamWaitEvent(0, evScan, 0);
    attn_kernel<<<dim3(Sv/64, BHv), 128, ATT_BYTES>>>(qkvoP, ab, Gb, nfl, mh_w, houtP);

    cudaStreamWaitEvent(0, evW2, 0);
    tgemm_kernel<1><<<dim3(Dv/128, Mv/256), 256, GSMEM>>>(houtP, wouth, x, nullptr, x1, nullptr, Dv, Dv);

    rmsnorm_kernel<0><<<Mv, 256>>>(x1, norm2_w, nullptr, h2P);

    tgemm_kernel<3><<<dim3(FFv/128, Mv/256), 256, GSMEM>>>(h2P, wgh, nullptr, nullptr, nullptr, gateP, FFv, Dv);
    tgemm_kernel<4><<<dim3(FFv/128, Mv/256), 256, GSMEM>>>(h2P, wuh, nullptr, gateP, nullptr, actP, FFv, Dv);

    // split-K=4 down-projection with fp16 partials, then fused residual add
    tgemm_kernel<6><<<dim3(Dv/128, Mv/256, KSPL), 256, GSMEM>>>(actP, wdh, nullptr, nullptr, nullptr, partP, Dv, FFv);
    addred_kernel<<<(Mv*Dv)/(256*4), 256>>>(x1, partP, out);

    (void)in_sizes; (void)n_in; (void)out_size;
}